// round 5
// baseline (speedup 1.0000x reference)
#include <cuda_runtime.h>
#include <cstdint>

// PScan: Y_t = A_t @ Y_{t-1} + X_t  (Y_0 = X_0), per (b,c) chain.
// Shapes: A,X,Y = [B=4, L=2048, C=16, 16, 16] fp32, row-major.
// Chunked scan (TT=16), cp.async staging, f32x2 FFMA, split-k half-warps,
// deep-pipelined phase2, bulk-store phase3.

#define BB 4
#define LL 2048
#define CC 16
#define TT 16
#define NCHUNK (LL / TT)            // 128
#define CHAINS (BB * CC)            // 64
#define TOTCHUNK (CHAINS * NCHUNK)  // 8192
#define STEP_STRIDE (CC * 256)

typedef unsigned long long u64;

__device__ float g_Pagg[TOTCHUNK * 256];
__device__ float g_Zagg[TOTCHUNK * 256];
__device__ float g_carry[TOTCHUNK * 256];

__device__ __forceinline__ u64 ffma2(u64 a, u64 b, u64 c) {
    u64 d;
    asm("fma.rn.f32x2 %0, %1, %2, %3;" : "=l"(d) : "l"(a), "l"(b), "l"(c));
    return d;
}
__device__ __forceinline__ u64 add2(u64 a, u64 b) {
    u64 d;
    asm("add.rn.f32x2 %0, %1, %2;" : "=l"(d) : "l"(a), "l"(b));
    return d;
}
__device__ __forceinline__ u64 pack2(float lo, float hi) {
    u64 d;
    asm("mov.b64 %0, {%1, %2};" : "=l"(d) : "f"(lo), "f"(hi));
    return d;
}
__device__ __forceinline__ void unpack2(u64 v, float& lo, float& hi) {
    asm("mov.b64 {%0, %1}, %2;" : "=f"(lo), "=f"(hi) : "l"(v));
}

__device__ __forceinline__ void cp16(float* smem_dst, const float* gsrc) {
    uint32_t s = (uint32_t)__cvta_generic_to_shared(smem_dst);
    asm volatile("cp.async.ca.shared.global [%0], [%1], 16;\n" :: "r"(s), "l"(gsrc));
}
#define CP_COMMIT() asm volatile("cp.async.commit_group;\n" ::: "memory")
#define CP_WAIT1()  asm volatile("cp.async.wait_group 1;\n" ::: "memory")
#define CP_WAIT0()  asm volatile("cp.async.wait_group 0;\n" ::: "memory")
#define CP_WAIT7()  asm volatile("cp.async.wait_group 7;\n" ::: "memory")

// bulk smem -> global store (async proxy), 1KB
__device__ __forceinline__ void bulk_store_1k(float* gdst, const float* ssrc) {
    uint32_t s = (uint32_t)__cvta_generic_to_shared(ssrc);
    asm volatile("cp.async.bulk.global.shared::cta.bulk_group [%0], [%1], %2;"
                 :: "l"(gdst), "r"(s), "r"(1024u) : "memory");
}
#define BULK_COMMIT()     asm volatile("cp.async.bulk.commit_group;" ::: "memory")
#define BULK_WAIT_READ1() asm volatile("cp.async.bulk.wait_group.read 1;" ::: "memory")
#define FENCE_ASYNC()     asm volatile("fence.proxy.async.shared::cta;" ::: "memory")

// partial dot of one A-row k-half (a0,a1 = 4 f32x2) with packed state st[4]
__device__ __forceinline__ float dot8(ulonglong2 a0, ulonglong2 a1, const u64* st)
{
    u64 acc0 = ffma2(a0.x, st[0], 0ull);
    u64 acc1 = ffma2(a0.y, st[1], 0ull);
    acc0 = ffma2(a1.x, st[2], acc0);
    acc1 = ffma2(a1.y, st[3], acc1);
    float lo, hi;
    unpack2(add2(acc0, acc1), lo, hi);
    return lo + hi;
}

// ============================================================================
// Phase 1: chunk aggregates. One warp per chunk; 64-thread blocks.
// Lane (j,h): k-half-h partials of Z[:,j] and P[:,j]; combine via shfl.xor(16).
// ============================================================================
__global__ void __launch_bounds__(64) phase1_kernel(
    const float* __restrict__ A, const float* __restrict__ X)
{
    __shared__ __align__(16) float sm[2][2][512];  // [warp][buf][A:256|X:256]

    const int wid  = threadIdx.x >> 5;
    const int lane = threadIdx.x & 31;
    const int w    = blockIdx.x * 2 + wid;
    const int chain = w / NCHUNK;
    const int chunk = w % NCHUNK;
    const int b = chain >> 4;
    const int c = chain & 15;
    const int t0 = chunk * TT;
    const int j = lane & 15;
    const int h = lane >> 4;

    const int base0 = ((b * LL + t0) * CC + c) * 256;
    const float* src = (h == 0 ? A : X) + base0 + j * 4;
    float* dst0 = sm[wid][0] + (h == 0 ? 0 : 256) + j * 4;
    float* dst1 = sm[wid][1] + (h == 0 ? 0 : 256) + j * 4;

#pragma unroll
    for (int q = 0; q < 4; q++) cp16(dst0 + q * 64, src + q * 64);
    CP_COMMIT();

    u64 zst[4], pst[4];
#pragma unroll
    for (int mm = 0; mm < 4; mm++) {
        zst[mm] = 0ull;
        int k0 = 8 * h + 2 * mm;
        pst[mm] = pack2(j == k0 ? 1.f : 0.f, j == k0 + 1 ? 1.f : 0.f);
    }

#pragma unroll 1
    for (int t = 0; t < TT; t++) {
        if (t + 1 < TT) {
            const float* s2 = src + (t + 1) * STEP_STRIDE;
            float* dn = (t & 1) ? dst0 : dst1;
#pragma unroll
            for (int q = 0; q < 4; q++) cp16(dn + q * 64, s2 + q * 64);
            CP_COMMIT();
            CP_WAIT1();
        } else {
            CP_WAIT0();
        }
        __syncwarp();

        const float* As = sm[wid][t & 1];
        const float* Xs = As + 256;
        const float* Ah = As + h * 8;

        float zpL[8], zpH[8], ppL[8], ppH[8];
#pragma unroll
        for (int r = 0; r < 8; r++) {
            ulonglong2 a0 = *(const ulonglong2*)(Ah + r * 16);
            ulonglong2 a1 = *(const ulonglong2*)(Ah + r * 16 + 4);
            zpL[r] = dot8(a0, a1, zst);
            ppL[r] = dot8(a0, a1, pst);
            ulonglong2 b0 = *(const ulonglong2*)(Ah + (8 + r) * 16);
            ulonglong2 b1 = *(const ulonglong2*)(Ah + (8 + r) * 16 + 4);
            zpH[r] = dot8(b0, b1, zst);
            ppH[r] = dot8(b0, b1, pst);
        }

        float zn[8], pn[8];
#pragma unroll
        for (int r = 0; r < 8; r++) {
            float zsend = h ? zpL[r] : zpH[r];
            float zrecv = __shfl_xor_sync(0xffffffffu, zsend, 16);
            float zown  = h ? zpH[r] : zpL[r];
            float xv = Xs[(8 * h + r) * 16 + j];
            zn[r] = zown + zrecv + xv;

            float psend = h ? ppL[r] : ppH[r];
            float precv = __shfl_xor_sync(0xffffffffu, psend, 16);
            float pown  = h ? ppH[r] : ppL[r];
            pn[r] = pown + precv;
        }
#pragma unroll
        for (int mm = 0; mm < 4; mm++) {
            zst[mm] = pack2(zn[2 * mm], zn[2 * mm + 1]);
            pst[mm] = pack2(pn[2 * mm], pn[2 * mm + 1]);
        }
        __syncwarp();
    }

    const int ab = w * 256;
#pragma unroll
    for (int mm = 0; mm < 4; mm++) {
        const int row = 8 * h + 2 * mm;
        float lo, hi;
        unpack2(zst[mm], lo, hi);
        g_Zagg[ab + row * 16 + j] = lo;
        g_Zagg[ab + (row + 1) * 16 + j] = hi;
        unpack2(pst[mm], lo, hi);
        g_Pagg[ab + row * 16 + j] = lo;
        g_Pagg[ab + (row + 1) * 16 + j] = hi;
    }
}

// ============================================================================
// Phase 2: per-chain scan of NCHUNK aggregates, depth-8 cp.async pipeline.
// ============================================================================
#define P2D 8

__global__ void phase2_kernel()
{
    __shared__ __align__(16) float sP[P2D][256];
    __shared__ __align__(16) float sZ[P2D][256];

    const int chain = blockIdx.x;
    const int lane  = threadIdx.x;
    const int col   = lane & 15;
    const bool zside = (lane < 16);

    const float* Pbase = g_Pagg + (size_t)chain * NCHUNK * 256;
    const float* Zbase = g_Zagg + (size_t)chain * NCHUNK * 256;

    // prologue: stage chunks 0..P2D-2
#pragma unroll 1
    for (int d = 0; d < P2D - 1; d++) {
        cp16(sP[d] + lane * 8,     Pbase + d * 256 + lane * 8);
        cp16(sP[d] + lane * 8 + 4, Pbase + d * 256 + lane * 8 + 4);
        cp16(sZ[d] + lane * 8,     Zbase + d * 256 + lane * 8);
        cp16(sZ[d] + lane * 8 + 4, Zbase + d * 256 + lane * 8 + 4);
        CP_COMMIT();
    }

    u64 ypk[8];
#pragma unroll
    for (int m = 0; m < 8; m++) ypk[m] = 0ull;

#pragma unroll 1
    for (int cix = 0; cix < NCHUNK; cix++) {
        const int buf = cix & (P2D - 1);
        const int pre = cix + P2D - 1;
        if (pre < NCHUNK) {
            const int pb = pre & (P2D - 1);
            cp16(sP[pb] + lane * 8,     Pbase + pre * 256 + lane * 8);
            cp16(sP[pb] + lane * 8 + 4, Pbase + pre * 256 + lane * 8 + 4);
            cp16(sZ[pb] + lane * 8,     Zbase + pre * 256 + lane * 8);
            cp16(sZ[pb] + lane * 8 + 4, Zbase + pre * 256 + lane * 8 + 4);
        }
        CP_COMMIT();   // unconditional: keeps group count aligned
        CP_WAIT7();
        __syncwarp();

        if (zside) {
            const int base = (chain * NCHUNK + cix) * 256;
            float cl[16];
#pragma unroll
            for (int m = 0; m < 8; m++) unpack2(ypk[m], cl[2 * m], cl[2 * m + 1]);
#pragma unroll
            for (int i = 0; i < 16; i++) g_carry[base + i * 16 + col] = cl[i];

            float yn[16];
#pragma unroll
            for (int i = 0; i < 16; i++) {
                const ulonglong2* pr = (const ulonglong2*)(sP[buf] + i * 16);
                ulonglong2 a0 = pr[0], a1 = pr[1], a2 = pr[2], a3 = pr[3];
                u64 acc0 = ffma2(a0.x, ypk[0], 0ull);
                u64 acc1 = ffma2(a2.x, ypk[4], 0ull);
                acc0 = ffma2(a0.y, ypk[1], acc0);
                acc1 = ffma2(a2.y, ypk[5], acc1);
                acc0 = ffma2(a1.x, ypk[2], acc0);
                acc1 = ffma2(a3.x, ypk[6], acc1);
                acc0 = ffma2(a1.y, ypk[3], acc0);
                acc1 = ffma2(a3.y, ypk[7], acc1);
                float lo, hi;
                unpack2(add2(acc0, acc1), lo, hi);
                yn[i] = lo + hi + sZ[buf][i * 16 + col];
            }
#pragma unroll
            for (int m = 0; m < 8; m++) ypk[m] = pack2(yn[2 * m], yn[2 * m + 1]);
        }
        __syncwarp();
    }
}

// ============================================================================
// Phase 3: final pass, split-k. Y staged row-major in smem (conflict-free
// parity-swapped STS.32), written out via cp.async.bulk (1KB per step).
// ============================================================================
__global__ void __launch_bounds__(64) phase3_kernel(
    const float* __restrict__ A, const float* __restrict__ X,
    float* __restrict__ Y)
{
    __shared__ __align__(16) float sm[2][2][512];
    __shared__ __align__(16) float syb[2][2][256];

    const int wid  = threadIdx.x >> 5;
    const int lane = threadIdx.x & 31;
    const int w    = blockIdx.x * 2 + wid;
    const int chain = w / NCHUNK;
    const int chunk = w % NCHUNK;
    const int b = chain >> 4;
    const int c = chain & 15;
    const int t0 = chunk * TT;
    const int j = lane & 15;
    const int h = lane >> 4;

    const int base0 = ((b * LL + t0) * CC + c) * 256;
    const float* src = (h == 0 ? A : X) + base0 + j * 4;
    float* dst0 = sm[wid][0] + (h == 0 ? 0 : 256) + j * 4;
    float* dst1 = sm[wid][1] + (h == 0 ? 0 : 256) + j * 4;

#pragma unroll
    for (int q = 0; q < 4; q++) cp16(dst0 + q * 64, src + q * 64);
    CP_COMMIT();

    // init state from carry: rows [8h, 8h+8) of column j
    u64 zst[4];
    {
        const int cb = w * 256;
#pragma unroll
        for (int mm = 0; mm < 4; mm++) {
            const int row = 8 * h + 2 * mm;
            zst[mm] = pack2(g_carry[cb + row * 16 + j],
                            g_carry[cb + (row + 1) * 16 + j]);
        }
    }

#pragma unroll 1
    for (int t = 0; t < TT; t++) {
        if (t + 1 < TT) {
            const float* s2 = src + (t + 1) * STEP_STRIDE;
            float* dn = (t & 1) ? dst0 : dst1;
#pragma unroll
            for (int q = 0; q < 4; q++) cp16(dn + q * 64, s2 + q * 64);
            CP_COMMIT();
            CP_WAIT1();
        } else {
            CP_WAIT0();
        }
        // free the y staging buffer (bulk from step t-2 must have read it)
        if (lane == 0) BULK_WAIT_READ1();
        __syncwarp();

        const float* As = sm[wid][t & 1];
        const float* Xs = As + 256;
        const float* Ah = As + h * 8;
        float* yb = syb[wid][t & 1];

        float zpL[8], zpH[8];
#pragma unroll
        for (int r = 0; r < 8; r++) {
            ulonglong2 a0 = *(const ulonglong2*)(Ah + r * 16);
            ulonglong2 a1 = *(const ulonglong2*)(Ah + r * 16 + 4);
            zpL[r] = dot8(a0, a1, zst);
            ulonglong2 b0 = *(const ulonglong2*)(Ah + (8 + r) * 16);
            ulonglong2 b1 = *(const ulonglong2*)(Ah + (8 + r) * 16 + 4);
            zpH[r] = dot8(b0, b1, zst);
        }

        float zn[8];
#pragma unroll
        for (int r = 0; r < 8; r++) {
            float zsend = h ? zpL[r] : zpH[r];
            float zrecv = __shfl_xor_sync(0xffffffffu, zsend, 16);
            float zown  = h ? zpH[r] : zpL[r];
            float xv = Xs[(8 * h + r) * 16 + j];
            zn[r] = zown + zrecv + xv;
        }
#pragma unroll
        for (int mm = 0; mm < 4; mm++)
            zst[mm] = pack2(zn[2 * mm], zn[2 * mm + 1]);

        // stage Y_t row-major; h=1 lanes use parity-swapped r to avoid bank
        // conflicts with h=0 lanes (rows i and i+8 share banks mod 32 floats)
#pragma unroll
        for (int r = 0; r < 8; r++) {
            const int rr = h ? (r ^ 1) : r;
            yb[(8 * h + rr) * 16 + j] = zn[rr];
        }
        FENCE_ASYNC();
        __syncwarp();

        if (lane == 0) {
            bulk_store_1k(Y + base0 + t * STEP_STRIDE, yb);
            BULK_COMMIT();
        }
    }
}

// ============================================================================
extern "C" void kernel_launch(void* const* d_in, const int* in_sizes, int n_in,
                              void* d_out, int out_size)
{
    const float* A = (const float*)d_in[0];
    const float* X = (const float*)d_in[1];
    float* Y = (float*)d_out;

    phase1_kernel<<<TOTCHUNK / 2, 64>>>(A, X);
    phase2_kernel<<<CHAINS, 32>>>();
    phase3_kernel<<<TOTCHUNK / 2, 64>>>(A, X, Y);
}

// round 6
// speedup vs baseline: 1.1832x; 1.1832x over previous
#include <cuda_runtime.h>
#include <cstdint>

// PScan: Y_t = A_t @ Y_{t-1} + X_t  (Y_0 = X_0), per (b,c) chain.
// Shapes: A,X,Y = [B=4, L=2048, C=16, 16, 16] fp32, row-major.
// Chunked scan (TT=32), depth-4 cp.async ring, f32x2 FFMA, split-k half-warps.

#define BB 4
#define LL 2048
#define CC 16
#define TT 32
#define NCHUNK (LL / TT)            // 64
#define CHAINS (BB * CC)            // 64
#define TOTCHUNK (CHAINS * NCHUNK)  // 4096
#define STEP_STRIDE (CC * 256)

typedef unsigned long long u64;

__device__ float g_Pagg[TOTCHUNK * 256];
__device__ float g_Zagg[TOTCHUNK * 256];
__device__ float g_carry[TOTCHUNK * 256];

__device__ __forceinline__ u64 ffma2(u64 a, u64 b, u64 c) {
    u64 d;
    asm("fma.rn.f32x2 %0, %1, %2, %3;" : "=l"(d) : "l"(a), "l"(b), "l"(c));
    return d;
}
__device__ __forceinline__ u64 add2(u64 a, u64 b) {
    u64 d;
    asm("add.rn.f32x2 %0, %1, %2;" : "=l"(d) : "l"(a), "l"(b));
    return d;
}
__device__ __forceinline__ u64 pack2(float lo, float hi) {
    u64 d;
    asm("mov.b64 %0, {%1, %2};" : "=l"(d) : "f"(lo), "f"(hi));
    return d;
}
__device__ __forceinline__ void unpack2(u64 v, float& lo, float& hi) {
    asm("mov.b64 {%0, %1}, %2;" : "=f"(lo), "=f"(hi) : "l"(v));
}

__device__ __forceinline__ void cp16(float* smem_dst, const float* gsrc) {
    uint32_t s = (uint32_t)__cvta_generic_to_shared(smem_dst);
    asm volatile("cp.async.ca.shared.global [%0], [%1], 16;\n" :: "r"(s), "l"(gsrc));
}
#define CP_COMMIT() asm volatile("cp.async.commit_group;\n" ::: "memory")
#define CP_WAIT3()  asm volatile("cp.async.wait_group 3;\n" ::: "memory")
#define CP_WAIT7()  asm volatile("cp.async.wait_group 7;\n" ::: "memory")

// partial dot of one A-row k-half (a0,a1 = 4 f32x2) with packed state st[4]
__device__ __forceinline__ float dot8(ulonglong2 a0, ulonglong2 a1, const u64* st)
{
    u64 acc0 = ffma2(a0.x, st[0], 0ull);
    u64 acc1 = ffma2(a0.y, st[1], 0ull);
    acc0 = ffma2(a1.x, st[2], acc0);
    acc1 = ffma2(a1.y, st[3], acc1);
    float lo, hi;
    unpack2(add2(acc0, acc1), lo, hi);
    return lo + hi;
}

// ============================================================================
// Phase 1: chunk aggregates. One warp per chunk; 64-thread blocks.
// Lane (j,h): k-half-h partials of Z[:,j] and P[:,j]; combine via shfl.xor(16).
// A_t/X_t staged through a depth-4 cp.async ring.
// ============================================================================
__global__ void __launch_bounds__(64) phase1_kernel(
    const float* __restrict__ A, const float* __restrict__ X)
{
    __shared__ __align__(16) float sm[2][4][512];  // [warp][ringbuf][A:256|X:256]

    const int wid  = threadIdx.x >> 5;
    const int lane = threadIdx.x & 31;
    const int w    = blockIdx.x * 2 + wid;
    const int chain = w / NCHUNK;
    const int chunk = w % NCHUNK;
    const int b = chain >> 4;
    const int c = chain & 15;
    const int t0 = chunk * TT;
    const int j = lane & 15;
    const int h = lane >> 4;

    const int base0 = ((b * LL + t0) * CC + c) * 256;
    const float* src = (h == 0 ? A : X) + base0 + j * 4;
    const int soff = (h == 0 ? 0 : 256) + j * 4;

    // prologue: stage steps 0..2
#pragma unroll
    for (int d = 0; d < 3; d++) {
        float* dn = sm[wid][d] + soff;
        const float* s2 = src + d * STEP_STRIDE;
#pragma unroll
        for (int q = 0; q < 4; q++) cp16(dn + q * 64, s2 + q * 64);
        CP_COMMIT();
    }

    u64 zst[4], pst[4];
#pragma unroll
    for (int mm = 0; mm < 4; mm++) {
        zst[mm] = 0ull;
        int k0 = 8 * h + 2 * mm;
        pst[mm] = pack2(j == k0 ? 1.f : 0.f, j == k0 + 1 ? 1.f : 0.f);
    }

#pragma unroll 1
    for (int t = 0; t < TT; t++) {
        if (t + 3 < TT) {
            const float* s2 = src + (t + 3) * STEP_STRIDE;
            float* dn = sm[wid][(t + 3) & 3] + soff;
#pragma unroll
            for (int q = 0; q < 4; q++) cp16(dn + q * 64, s2 + q * 64);
        }
        CP_COMMIT();      // unconditional: group count stays aligned
        CP_WAIT3();       // step-t group complete
        __syncwarp();

        const float* As = sm[wid][t & 3];
        const float* Xs = As + 256;
        const float* Ah = As + h * 8;

        float zpL[8], zpH[8], ppL[8], ppH[8];
#pragma unroll
        for (int r = 0; r < 8; r++) {
            ulonglong2 a0 = *(const ulonglong2*)(Ah + r * 16);
            ulonglong2 a1 = *(const ulonglong2*)(Ah + r * 16 + 4);
            zpL[r] = dot8(a0, a1, zst);
            ppL[r] = dot8(a0, a1, pst);
            ulonglong2 b0 = *(const ulonglong2*)(Ah + (8 + r) * 16);
            ulonglong2 b1 = *(const ulonglong2*)(Ah + (8 + r) * 16 + 4);
            zpH[r] = dot8(b0, b1, zst);
            ppH[r] = dot8(b0, b1, pst);
        }

        float zn[8], pn[8];
#pragma unroll
        for (int r = 0; r < 8; r++) {
            float zsend = h ? zpL[r] : zpH[r];
            float zrecv = __shfl_xor_sync(0xffffffffu, zsend, 16);
            float zown  = h ? zpH[r] : zpL[r];
            float xv = Xs[(8 * h + r) * 16 + j];
            zn[r] = zown + zrecv + xv;

            float psend = h ? ppL[r] : ppH[r];
            float precv = __shfl_xor_sync(0xffffffffu, psend, 16);
            float pown  = h ? ppH[r] : ppL[r];
            pn[r] = pown + precv;
        }
#pragma unroll
        for (int mm = 0; mm < 4; mm++) {
            zst[mm] = pack2(zn[2 * mm], zn[2 * mm + 1]);
            pst[mm] = pack2(pn[2 * mm], pn[2 * mm + 1]);
        }
    }

    const int ab = w * 256;
#pragma unroll
    for (int mm = 0; mm < 4; mm++) {
        const int row = 8 * h + 2 * mm;
        float lo, hi;
        unpack2(zst[mm], lo, hi);
        g_Zagg[ab + row * 16 + j] = lo;
        g_Zagg[ab + (row + 1) * 16 + j] = hi;
        unpack2(pst[mm], lo, hi);
        g_Pagg[ab + row * 16 + j] = lo;
        g_Pagg[ab + (row + 1) * 16 + j] = hi;
    }
}

// ============================================================================
// Phase 2: per-chain scan of NCHUNK aggregates, depth-8 cp.async pipeline.
// ============================================================================
#define P2D 8

__global__ void phase2_kernel()
{
    __shared__ __align__(16) float sP[P2D][256];
    __shared__ __align__(16) float sZ[P2D][256];

    const int chain = blockIdx.x;
    const int lane  = threadIdx.x;
    const int col   = lane & 15;
    const bool zside = (lane < 16);

    const float* Pbase = g_Pagg + (size_t)chain * NCHUNK * 256;
    const float* Zbase = g_Zagg + (size_t)chain * NCHUNK * 256;

#pragma unroll 1
    for (int d = 0; d < P2D - 1; d++) {
        cp16(sP[d] + lane * 8,     Pbase + d * 256 + lane * 8);
        cp16(sP[d] + lane * 8 + 4, Pbase + d * 256 + lane * 8 + 4);
        cp16(sZ[d] + lane * 8,     Zbase + d * 256 + lane * 8);
        cp16(sZ[d] + lane * 8 + 4, Zbase + d * 256 + lane * 8 + 4);
        CP_COMMIT();
    }

    u64 ypk[8];
#pragma unroll
    for (int m = 0; m < 8; m++) ypk[m] = 0ull;

#pragma unroll 1
    for (int cix = 0; cix < NCHUNK; cix++) {
        const int buf = cix & (P2D - 1);
        const int pre = cix + P2D - 1;
        if (pre < NCHUNK) {
            const int pb = pre & (P2D - 1);
            cp16(sP[pb] + lane * 8,     Pbase + pre * 256 + lane * 8);
            cp16(sP[pb] + lane * 8 + 4, Pbase + pre * 256 + lane * 8 + 4);
            cp16(sZ[pb] + lane * 8,     Zbase + pre * 256 + lane * 8);
            cp16(sZ[pb] + lane * 8 + 4, Zbase + pre * 256 + lane * 8 + 4);
        }
        CP_COMMIT();
        CP_WAIT7();
        __syncwarp();

        if (zside) {
            const int base = (chain * NCHUNK + cix) * 256;
            float cl[16];
#pragma unroll
            for (int m = 0; m < 8; m++) unpack2(ypk[m], cl[2 * m], cl[2 * m + 1]);
#pragma unroll
            for (int i = 0; i < 16; i++) g_carry[base + i * 16 + col] = cl[i];

            float yn[16];
#pragma unroll
            for (int i = 0; i < 16; i++) {
                const ulonglong2* pr = (const ulonglong2*)(sP[buf] + i * 16);
                ulonglong2 a0 = pr[0], a1 = pr[1], a2 = pr[2], a3 = pr[3];
                u64 acc0 = ffma2(a0.x, ypk[0], 0ull);
                u64 acc1 = ffma2(a2.x, ypk[4], 0ull);
                acc0 = ffma2(a0.y, ypk[1], acc0);
                acc1 = ffma2(a2.y, ypk[5], acc1);
                acc0 = ffma2(a1.x, ypk[2], acc0);
                acc1 = ffma2(a3.x, ypk[6], acc1);
                acc0 = ffma2(a1.y, ypk[3], acc0);
                acc1 = ffma2(a3.y, ypk[7], acc1);
                float lo, hi;
                unpack2(add2(acc0, acc1), lo, hi);
                yn[i] = lo + hi + sZ[buf][i * 16 + col];
            }
#pragma unroll
            for (int m = 0; m < 8; m++) ypk[m] = pack2(yn[2 * m], yn[2 * m + 1]);
        }
        __syncwarp();
    }
}

// ============================================================================
// Phase 3: final pass, split-k, depth-4 ring. Y staged via padded smem
// transpose (single buffer, lockstep warp) -> 2 coalesced STG.128 per step.
// ============================================================================
#define YP 18

__global__ void __launch_bounds__(64) phase3_kernel(
    const float* __restrict__ A, const float* __restrict__ X,
    float* __restrict__ Y)
{
    __shared__ __align__(16) float sm[2][4][512];
    __shared__ __align__(16) float sy[2][16 * YP];

    const int wid  = threadIdx.x >> 5;
    const int lane = threadIdx.x & 31;
    const int w    = blockIdx.x * 2 + wid;
    const int chain = w / NCHUNK;
    const int chunk = w % NCHUNK;
    const int b = chain >> 4;
    const int c = chain & 15;
    const int t0 = chunk * TT;
    const int j = lane & 15;
    const int h = lane >> 4;

    const int base0 = ((b * LL + t0) * CC + c) * 256;
    const float* src = (h == 0 ? A : X) + base0 + j * 4;
    const int soff = (h == 0 ? 0 : 256) + j * 4;

#pragma unroll
    for (int d = 0; d < 3; d++) {
        float* dn = sm[wid][d] + soff;
        const float* s2 = src + d * STEP_STRIDE;
#pragma unroll
        for (int q = 0; q < 4; q++) cp16(dn + q * 64, s2 + q * 64);
        CP_COMMIT();
    }

    // init state from carry: rows [8h, 8h+8) of column j
    u64 zst[4];
    {
        const int cb = w * 256;
#pragma unroll
        for (int mm = 0; mm < 4; mm++) {
            const int row = 8 * h + 2 * mm;
            zst[mm] = pack2(g_carry[cb + row * 16 + j],
                            g_carry[cb + (row + 1) * 16 + j]);
        }
    }

    const int e0a = lane * 4;
    const int e0b = 128 + lane * 4;
    float* Ys = sy[wid];

#pragma unroll 1
    for (int t = 0; t < TT; t++) {
        if (t + 3 < TT) {
            const float* s2 = src + (t + 3) * STEP_STRIDE;
            float* dn = sm[wid][(t + 3) & 3] + soff;
#pragma unroll
            for (int q = 0; q < 4; q++) cp16(dn + q * 64, s2 + q * 64);
        }
        CP_COMMIT();
        CP_WAIT3();
        __syncwarp();

        const float* As = sm[wid][t & 3];
        const float* Xs = As + 256;
        const float* Ah = As + h * 8;

        float zpL[8], zpH[8];
#pragma unroll
        for (int r = 0; r < 8; r++) {
            ulonglong2 a0 = *(const ulonglong2*)(Ah + r * 16);
            ulonglong2 a1 = *(const ulonglong2*)(Ah + r * 16 + 4);
            zpL[r] = dot8(a0, a1, zst);
            ulonglong2 b0 = *(const ulonglong2*)(Ah + (8 + r) * 16);
            ulonglong2 b1 = *(const ulonglong2*)(Ah + (8 + r) * 16 + 4);
            zpH[r] = dot8(b0, b1, zst);
        }

        float zn[8];
#pragma unroll
        for (int r = 0; r < 8; r++) {
            float zsend = h ? zpL[r] : zpH[r];
            float zrecv = __shfl_xor_sync(0xffffffffu, zsend, 16);
            float zown  = h ? zpH[r] : zpL[r];
            float xv = Xs[(8 * h + r) * 16 + j];
            zn[r] = zown + zrecv + xv;
        }
#pragma unroll
        for (int mm = 0; mm < 4; mm++)
            zst[mm] = pack2(zn[2 * mm], zn[2 * mm + 1]);

        // stage rows [8h,8h+8) of column j into padded transpose buffer
        {
            u64* yc = (u64*)(Ys + j * YP + 8 * h);
#pragma unroll
            for (int mm = 0; mm < 4; mm++) yc[mm] = zst[mm];
        }
        __syncwarp();

        // coalesced write of Y_t (1KB contiguous) by all 32 lanes
        {
            float* out = Y + base0 + t * STEP_STRIDE;
            float4 v;
            int i = e0a >> 4, c0 = e0a & 15;
            v.x = Ys[(c0 + 0) * YP + i];
            v.y = Ys[(c0 + 1) * YP + i];
            v.z = Ys[(c0 + 2) * YP + i];
            v.w = Ys[(c0 + 3) * YP + i];
            *(float4*)(out + e0a) = v;
            i = e0b >> 4; c0 = e0b & 15;
            v.x = Ys[(c0 + 0) * YP + i];
            v.y = Ys[(c0 + 1) * YP + i];
            v.z = Ys[(c0 + 2) * YP + i];
            v.w = Ys[(c0 + 3) * YP + i];
            *(float4*)(out + e0b) = v;
        }
        __syncwarp();
    }
}

// ============================================================================
extern "C" void kernel_launch(void* const* d_in, const int* in_sizes, int n_in,
                              void* d_out, int out_size)
{
    const float* A = (const float*)d_in[0];
    const float* X = (const float*)d_in[1];
    float* Y = (float*)d_out;

    phase1_kernel<<<TOTCHUNK / 2, 64>>>(A, X);
    phase2_kernel<<<CHAINS, 32>>>();
    phase3_kernel<<<TOTCHUNK / 2, 64>>>(A, X, Y);
}

// round 7
// speedup vs baseline: 1.2496x; 1.0561x over previous
#include <cuda_runtime.h>
#include <cstdint>

// PScan: Y_t = A_t @ Y_{t-1} + X_t  (Y_0 = X_0), per (b,c) chain.
// Shapes: A,X,Y = [B=4, L=2048, C=16, 16, 16] fp32, row-major.
// Chunked scan (TT=32), cp.async staging, f32x2 FFMA, split-k half-warps.
// Phase3 writes Y directly from registers (streaming STG.32).

#define BB 4
#define LL 2048
#define CC 16
#define TT 32
#define NCHUNK (LL / TT)            // 64
#define CHAINS (BB * CC)            // 64
#define TOTCHUNK (CHAINS * NCHUNK)  // 4096
#define STEP_STRIDE (CC * 256)

typedef unsigned long long u64;

__device__ float g_Pagg[TOTCHUNK * 256];
__device__ float g_Zagg[TOTCHUNK * 256];
__device__ float g_carry[TOTCHUNK * 256];

__device__ __forceinline__ u64 ffma2(u64 a, u64 b, u64 c) {
    u64 d;
    asm("fma.rn.f32x2 %0, %1, %2, %3;" : "=l"(d) : "l"(a), "l"(b), "l"(c));
    return d;
}
__device__ __forceinline__ u64 add2(u64 a, u64 b) {
    u64 d;
    asm("add.rn.f32x2 %0, %1, %2;" : "=l"(d) : "l"(a), "l"(b));
    return d;
}
__device__ __forceinline__ u64 pack2(float lo, float hi) {
    u64 d;
    asm("mov.b64 %0, {%1, %2};" : "=l"(d) : "f"(lo), "f"(hi));
    return d;
}
__device__ __forceinline__ void unpack2(u64 v, float& lo, float& hi) {
    asm("mov.b64 {%0, %1}, %2;" : "=f"(lo), "=f"(hi) : "l"(v));
}

__device__ __forceinline__ void cp16(float* smem_dst, const float* gsrc) {
    uint32_t s = (uint32_t)__cvta_generic_to_shared(smem_dst);
    asm volatile("cp.async.ca.shared.global [%0], [%1], 16;\n" :: "r"(s), "l"(gsrc));
}
#define CP_COMMIT() asm volatile("cp.async.commit_group;\n" ::: "memory")
#define CP_WAIT0()  asm volatile("cp.async.wait_group 0;\n" ::: "memory")
#define CP_WAIT1()  asm volatile("cp.async.wait_group 1;\n" ::: "memory")
#define CP_WAIT3()  asm volatile("cp.async.wait_group 3;\n" ::: "memory")
#define CP_WAIT7()  asm volatile("cp.async.wait_group 7;\n" ::: "memory")

// partial dot of one A-row k-half (a0,a1 = 4 f32x2) with packed state st[4]
__device__ __forceinline__ float dot8(ulonglong2 a0, ulonglong2 a1, const u64* st)
{
    u64 acc0 = ffma2(a0.x, st[0], 0ull);
    u64 acc1 = ffma2(a0.y, st[1], 0ull);
    acc0 = ffma2(a1.x, st[2], acc0);
    acc1 = ffma2(a1.y, st[3], acc1);
    float lo, hi;
    unpack2(add2(acc0, acc1), lo, hi);
    return lo + hi;
}

// ============================================================================
// Phase 1 (R4-proven): chunk aggregates, depth-2 double buffer.
// Lane (j,h): k-half-h partials of Z[:,j] and P[:,j]; combine via shfl.xor(16).
// ============================================================================
__global__ void __launch_bounds__(64) phase1_kernel(
    const float* __restrict__ A, const float* __restrict__ X)
{
    __shared__ __align__(16) float sm[2][2][512];  // [warp][buf][A:256|X:256]

    const int wid  = threadIdx.x >> 5;
    const int lane = threadIdx.x & 31;
    const int w    = blockIdx.x * 2 + wid;
    const int chain = w / NCHUNK;
    const int chunk = w % NCHUNK;
    const int b = chain >> 4;
    const int c = chain & 15;
    const int t0 = chunk * TT;
    const int j = lane & 15;
    const int h = lane >> 4;

    const int base0 = ((b * LL + t0) * CC + c) * 256;
    const float* src = (h == 0 ? A : X) + base0 + j * 4;
    float* dst0 = sm[wid][0] + (h == 0 ? 0 : 256) + j * 4;
    float* dst1 = sm[wid][1] + (h == 0 ? 0 : 256) + j * 4;

#pragma unroll
    for (int q = 0; q < 4; q++) cp16(dst0 + q * 64, src + q * 64);
    CP_COMMIT();

    u64 zst[4], pst[4];
#pragma unroll
    for (int mm = 0; mm < 4; mm++) {
        zst[mm] = 0ull;
        int k0 = 8 * h + 2 * mm;
        pst[mm] = pack2(j == k0 ? 1.f : 0.f, j == k0 + 1 ? 1.f : 0.f);
    }

#pragma unroll 1
    for (int t = 0; t < TT; t++) {
        if (t + 1 < TT) {
            const float* s2 = src + (t + 1) * STEP_STRIDE;
            float* dn = (t & 1) ? dst0 : dst1;
#pragma unroll
            for (int q = 0; q < 4; q++) cp16(dn + q * 64, s2 + q * 64);
            CP_COMMIT();
            CP_WAIT1();
        } else {
            CP_WAIT0();
        }
        __syncwarp();

        const float* As = sm[wid][t & 1];
        const float* Xs = As + 256;
        const float* Ah = As + h * 8;

        float zpL[8], zpH[8], ppL[8], ppH[8];
#pragma unroll
        for (int r = 0; r < 8; r++) {
            ulonglong2 a0 = *(const ulonglong2*)(Ah + r * 16);
            ulonglong2 a1 = *(const ulonglong2*)(Ah + r * 16 + 4);
            zpL[r] = dot8(a0, a1, zst);
            ppL[r] = dot8(a0, a1, pst);
            ulonglong2 b0 = *(const ulonglong2*)(Ah + (8 + r) * 16);
            ulonglong2 b1 = *(const ulonglong2*)(Ah + (8 + r) * 16 + 4);
            zpH[r] = dot8(b0, b1, zst);
            ppH[r] = dot8(b0, b1, pst);
        }

        float zn[8], pn[8];
#pragma unroll
        for (int r = 0; r < 8; r++) {
            float zsend = h ? zpL[r] : zpH[r];
            float zrecv = __shfl_xor_sync(0xffffffffu, zsend, 16);
            float zown  = h ? zpH[r] : zpL[r];
            float xv = Xs[(8 * h + r) * 16 + j];
            zn[r] = zown + zrecv + xv;

            float psend = h ? ppL[r] : ppH[r];
            float precv = __shfl_xor_sync(0xffffffffu, psend, 16);
            float pown  = h ? ppH[r] : ppL[r];
            pn[r] = pown + precv;
        }
#pragma unroll
        for (int mm = 0; mm < 4; mm++) {
            zst[mm] = pack2(zn[2 * mm], zn[2 * mm + 1]);
            pst[mm] = pack2(pn[2 * mm], pn[2 * mm + 1]);
        }
        __syncwarp();
    }

    const int ab = w * 256;
#pragma unroll
    for (int mm = 0; mm < 4; mm++) {
        const int row = 8 * h + 2 * mm;
        float lo, hi;
        unpack2(zst[mm], lo, hi);
        g_Zagg[ab + row * 16 + j] = lo;
        g_Zagg[ab + (row + 1) * 16 + j] = hi;
        unpack2(pst[mm], lo, hi);
        g_Pagg[ab + row * 16 + j] = lo;
        g_Pagg[ab + (row + 1) * 16 + j] = hi;
    }
}

// ============================================================================
// Phase 2: per-chain scan of NCHUNK aggregates, depth-8 cp.async pipeline.
// ============================================================================
#define P2D 8

__global__ void phase2_kernel()
{
    __shared__ __align__(16) float sP[P2D][256];
    __shared__ __align__(16) float sZ[P2D][256];

    const int chain = blockIdx.x;
    const int lane  = threadIdx.x;
    const int col   = lane & 15;
    const bool zside = (lane < 16);

    const float* Pbase = g_Pagg + (size_t)chain * NCHUNK * 256;
    const float* Zbase = g_Zagg + (size_t)chain * NCHUNK * 256;

#pragma unroll 1
    for (int d = 0; d < P2D - 1; d++) {
        cp16(sP[d] + lane * 8,     Pbase + d * 256 + lane * 8);
        cp16(sP[d] + lane * 8 + 4, Pbase + d * 256 + lane * 8 + 4);
        cp16(sZ[d] + lane * 8,     Zbase + d * 256 + lane * 8);
        cp16(sZ[d] + lane * 8 + 4, Zbase + d * 256 + lane * 8 + 4);
        CP_COMMIT();
    }

    u64 ypk[8];
#pragma unroll
    for (int m = 0; m < 8; m++) ypk[m] = 0ull;

#pragma unroll 1
    for (int cix = 0; cix < NCHUNK; cix++) {
        const int buf = cix & (P2D - 1);
        const int pre = cix + P2D - 1;
        if (pre < NCHUNK) {
            const int pb = pre & (P2D - 1);
            cp16(sP[pb] + lane * 8,     Pbase + pre * 256 + lane * 8);
            cp16(sP[pb] + lane * 8 + 4, Pbase + pre * 256 + lane * 8 + 4);
            cp16(sZ[pb] + lane * 8,     Zbase + pre * 256 + lane * 8);
            cp16(sZ[pb] + lane * 8 + 4, Zbase + pre * 256 + lane * 8 + 4);
        }
        CP_COMMIT();
        CP_WAIT7();
        __syncwarp();

        if (zside) {
            const int base = (chain * NCHUNK + cix) * 256;
            float cl[16];
#pragma unroll
            for (int m = 0; m < 8; m++) unpack2(ypk[m], cl[2 * m], cl[2 * m + 1]);
#pragma unroll
            for (int i = 0; i < 16; i++) g_carry[base + i * 16 + col] = cl[i];

            float yn[16];
#pragma unroll
            for (int i = 0; i < 16; i++) {
                const ulonglong2* pr = (const ulonglong2*)(sP[buf] + i * 16);
                ulonglong2 a0 = pr[0], a1 = pr[1], a2 = pr[2], a3 = pr[3];
                u64 acc0 = ffma2(a0.x, ypk[0], 0ull);
                u64 acc1 = ffma2(a2.x, ypk[4], 0ull);
                acc0 = ffma2(a0.y, ypk[1], acc0);
                acc1 = ffma2(a2.y, ypk[5], acc1);
                acc0 = ffma2(a1.x, ypk[2], acc0);
                acc1 = ffma2(a3.x, ypk[6], acc1);
                acc0 = ffma2(a1.y, ypk[3], acc0);
                acc1 = ffma2(a3.y, ypk[7], acc1);
                float lo, hi;
                unpack2(add2(acc0, acc1), lo, hi);
                yn[i] = lo + hi + sZ[buf][i * 16 + col];
            }
#pragma unroll
            for (int m = 0; m < 8; m++) ypk[m] = pack2(yn[2 * m], yn[2 * m + 1]);
        }
        __syncwarp();
    }
}

// ============================================================================
// Phase 3: final pass, split-k, depth-4 ring. Y written DIRECTLY from
// registers via streaming STG.32 (each warp-instruction covers two full
// 64B rows -> full sectors, no transpose round-trip, no extra barriers).
// ============================================================================
__global__ void __launch_bounds__(64) phase3_kernel(
    const float* __restrict__ A, const float* __restrict__ X,
    float* __restrict__ Y)
{
    __shared__ __align__(16) float sm[2][4][512];

    const int wid  = threadIdx.x >> 5;
    const int lane = threadIdx.x & 31;
    const int w    = blockIdx.x * 2 + wid;
    const int chain = w / NCHUNK;
    const int chunk = w % NCHUNK;
    const int b = chain >> 4;
    const int c = chain & 15;
    const int t0 = chunk * TT;
    const int j = lane & 15;
    const int h = lane >> 4;

    const int base0 = ((b * LL + t0) * CC + c) * 256;
    const float* src = (h == 0 ? A : X) + base0 + j * 4;
    const int soff = (h == 0 ? 0 : 256) + j * 4;

#pragma unroll
    for (int d = 0; d < 3; d++) {
        float* dn = sm[wid][d] + soff;
        const float* s2 = src + d * STEP_STRIDE;
#pragma unroll
        for (int q = 0; q < 4; q++) cp16(dn + q * 64, s2 + q * 64);
        CP_COMMIT();
    }

    // init state from carry: rows [8h, 8h+8) of column j
    u64 zst[4];
    {
        const int cb = w * 256;
#pragma unroll
        for (int mm = 0; mm < 4; mm++) {
            const int row = 8 * h + 2 * mm;
            zst[mm] = pack2(g_carry[cb + row * 16 + j],
                            g_carry[cb + (row + 1) * 16 + j]);
        }
    }

    // per-lane output base: column j, starting row 8h
    float* outc = Y + base0 + (8 * h) * 16 + j;

#pragma unroll 1
    for (int t = 0; t < TT; t++) {
        if (t + 3 < TT) {
            const float* s2 = src + (t + 3) * STEP_STRIDE;
            float* dn = sm[wid][(t + 3) & 3] + soff;
#pragma unroll
            for (int q = 0; q < 4; q++) cp16(dn + q * 64, s2 + q * 64);
        }
        CP_COMMIT();
        CP_WAIT3();
        __syncwarp();

        const float* As = sm[wid][t & 3];
        const float* Xs = As + 256;
        const float* Ah = As + h * 8;

        float zpL[8], zpH[8];
#pragma unroll
        for (int r = 0; r < 8; r++) {
            ulonglong2 a0 = *(const ulonglong2*)(Ah + r * 16);
            ulonglong2 a1 = *(const ulonglong2*)(Ah + r * 16 + 4);
            zpL[r] = dot8(a0, a1, zst);
            ulonglong2 b0 = *(const ulonglong2*)(Ah + (8 + r) * 16);
            ulonglong2 b1 = *(const ulonglong2*)(Ah + (8 + r) * 16 + 4);
            zpH[r] = dot8(b0, b1, zst);
        }

        float zn[8];
#pragma unroll
        for (int r = 0; r < 8; r++) {
            float zsend = h ? zpL[r] : zpH[r];
            float zrecv = __shfl_xor_sync(0xffffffffu, zsend, 16);
            float zown  = h ? zpH[r] : zpL[r];
            float xv = Xs[(8 * h + r) * 16 + j];
            zn[r] = zown + zrecv + xv;
        }
#pragma unroll
        for (int mm = 0; mm < 4; mm++)
            zst[mm] = pack2(zn[2 * mm], zn[2 * mm + 1]);

        // direct streaming store of this lane's 8 Y elements
        float* out = outc + t * STEP_STRIDE;
#pragma unroll
        for (int r = 0; r < 8; r++) __stcs(out + r * 16, zn[r]);
    }
}

// ============================================================================
extern "C" void kernel_launch(void* const* d_in, const int* in_sizes, int n_in,
                              void* d_out, int out_size)
{
    const float* A = (const float*)d_in[0];
    const float* X = (const float*)d_in[1];
    float* Y = (float*)d_out;

    phase1_kernel<<<TOTCHUNK / 2, 64>>>(A, X);
    phase2_kernel<<<CHAINS, 32>>>();
    phase3_kernel<<<TOTCHUNK / 2, 64>>>(A, X, Y);
}